// round 11
// baseline (speedup 1.0000x reference)
#include <cuda_runtime.h>
#include <cuda_bf16.h>
#include <cstdint>

#define BATCH   256
#define FEAT    512
#define HIDDEN  512
#define WVEC    256
#define VOCAB   32000
#define TSTEPS  16
#define CAPLEN  17
#define NRC     32          // recurrence CTAs (16 groups x 2 halves)
#define NGRP    16          // row groups
#define RPC     16          // batch rows per group
#define NTHR    512

// ---------------------------------------------------------------------------
// Fragment-native layout: element (row,k) of a [R][K] bf16 matrix lives at
//   ((row/8)*(K/32) + k/32)*256 + ((row%8)*4 + (k/8)%4)*8 + (k%8)   [elements]
// One warp's 8-row x 32-k fragment = 32 consecutive 16B granules (lane = slot).
// ---------------------------------------------------------------------------
__device__ __forceinline__ size_t frag_off(int row, int k, int K) {
    return ((size_t)(row >> 3) * (K >> 5) + (k >> 5)) * 256
         + (size_t)(((row & 7) * 4 + ((k >> 3) & 3)) * 8 + (k & 7));
}

// ---------------------------------------------------------------------------
// Scratch
// ---------------------------------------------------------------------------
constexpr size_t OFF_VOCABW  = 0;                                             // 32000x512 bf16
constexpr size_t OFF_WHH     = OFF_VOCABW  + (size_t)VOCAB * HIDDEN * 2;      // 2048x512
constexpr size_t OFF_WIH     = OFF_WHH     + (size_t)4 * HIDDEN * HIDDEN * 2; // 2048x256
constexpr size_t OFF_PROJW   = OFF_WIH     + (size_t)4 * HIDDEN * WVEC * 2;   // 512x512
constexpr size_t OFF_ATTNW   = OFF_PROJW   + (size_t)HIDDEN * FEAT * 2;       // 512x512
constexpr size_t OFF_ZTRANSW = OFF_ATTNW   + (size_t)FEAT * HIDDEN * 2;       // 256x512
constexpr size_t OFF_HBUF    = OFF_ZTRANSW + (size_t)WVEC * FEAT * 2;         // 16 x 256x512 bf16
constexpr size_t OFF_ROWSUM  = OFF_HBUF    + (size_t)TSTEPS * BATCH * HIDDEN * 2;
constexpr size_t OFF_TGTL    = OFF_ROWSUM  + (size_t)TSTEPS * BATCH * 4;
constexpr size_t OFF_FLAGS   = OFF_TGTL    + (size_t)TSTEPS * BATCH * 4;  // h_done[16]|vdone[16]|gxflag[32]
constexpr size_t OFF_GX      = OFF_FLAGS   + 256;                         // 16 grp x 2 x 16x1024 bf16
constexpr size_t SCRATCH_TOTAL = OFF_GX + (size_t)NGRP * 2 * RPC * 1024 * 2;

__device__ __align__(1024) unsigned char g_scratch[SCRATCH_TOTAL];

// smem carve (dynamic), bytes — recurrence CTAs
constexpr int SM_FEAT  = 0;       // 16x512 bf16 frag  (16K)
constexpr int SM_H     = 16384;   // 16x512 bf16 frag  (16K)
constexpr int SM_Z     = 32768;   // 16x512 bf16 frag  (16K)
constexpr int SM_X     = 49152;   // 16x256 bf16 frag  (8K)
constexpr int SM_PRE   = 57344;   // 16x512 f32        (32K)
constexpr int SM_G     = 90112;   // 16x2048 bf16 rowmajor (64K)
constexpr int SMEM_BYTES = 155648;

// ---------------------------------------------------------------------------
// mma.sync bf16 core
// ---------------------------------------------------------------------------
__device__ __forceinline__ float sigmoidf_(float x) { return 1.f / (1.f + __expf(-x)); }

__device__ __forceinline__ uint32_t bf2_to_u32(float lo, float hi) {
    __nv_bfloat162 b = __floats2bfloat162_rn(lo, hi);
    return *reinterpret_cast<uint32_t*>(&b);
}

__device__ __forceinline__ void mma16816(float c[4], uint32_t a0, uint32_t a1,
                                         uint32_t a2, uint32_t a3, uint32_t b0, uint32_t b1) {
    asm volatile(
        "mma.sync.aligned.m16n8k16.row.col.f32.bf16.bf16.f32 "
        "{%0,%1,%2,%3},{%4,%5,%6,%7},{%8,%9},{%0,%1,%2,%3};\n"
        : "+f"(c[0]), "+f"(c[1]), "+f"(c[2]), "+f"(c[3])
        : "r"(a0), "r"(a1), "r"(a2), "r"(a3), "r"(b0), "r"(b1));
}

// 16(M) x 32(N) warp tile, A frag in smem, B frag global. KB = K/32.
template <int KB>
__device__ __forceinline__ void tile16x32(const __nv_bfloat16* A, const __nv_bfloat16* B,
                                          int lane, float acc[4][4]) {
    const __nv_bfloat16* a0 = A + lane * 8;
    const __nv_bfloat16* a1 = A + KB * 256 + lane * 8;
    const __nv_bfloat16* bp = B + lane * 8;
    for (int it = 0; it < KB; it++) {
        uint4 al = *(const uint4*)(a0 + it * 256);
        uint4 ah = *(const uint4*)(a1 + it * 256);
#pragma unroll
        for (int ni = 0; ni < 4; ni++) {
            uint4 bv = *(const uint4*)(bp + (size_t)ni * KB * 256 + it * 256);
            mma16816(acc[ni], al.x, ah.x, al.y, ah.y, bv.x, bv.y);
            mma16816(acc[ni], al.z, ah.z, al.w, ah.w, bv.z, bv.w);
        }
    }
}

// 16(M) x 64(N) warp tile (half-gates), accumulating.
template <int KB>
__device__ __forceinline__ void tile16x64(const __nv_bfloat16* A, const __nv_bfloat16* B,
                                          int lane, float acc[8][4]) {
    const __nv_bfloat16* a0 = A + lane * 8;
    const __nv_bfloat16* a1 = A + KB * 256 + lane * 8;
    const __nv_bfloat16* bp = B + lane * 8;
    for (int it = 0; it < KB; it++) {
        uint4 al = *(const uint4*)(a0 + it * 256);
        uint4 ah = *(const uint4*)(a1 + it * 256);
#pragma unroll
        for (int ni = 0; ni < 8; ni++) {
            uint4 bv = *(const uint4*)(bp + (size_t)ni * KB * 256 + it * 256);
            mma16816(acc[ni], al.x, ah.x, al.y, ah.y, bv.x, bv.y);
            mma16816(acc[ni], al.z, ah.z, al.w, ah.w, bv.z, bv.w);
        }
    }
}

// ---------------------------------------------------------------------------
// Persistent heterogeneous kernel: CTAs 0..31 = recurrence pairs (each pair
// splits the gates GEMM by N), CTAs 32.. = vocab consumers.
// ---------------------------------------------------------------------------
__global__ void __launch_bounds__(NTHR)
mega_kernel(const float* __restrict__ features, const int* __restrict__ captions,
            const float* __restrict__ embed_W,
            const float* __restrict__ proj_b, const float* __restrict__ vocab_b,
            const float* __restrict__ attn_b, const float* __restrict__ ztrans_b,
            const float* __restrict__ b_ih, const float* __restrict__ b_hh,
            float* __restrict__ out)
{
    extern __shared__ char sp[];
    __shared__ int s_last;
    char* p = (char*)g_scratch;
    const __nv_bfloat16* vocabW  = (const __nv_bfloat16*)(p + OFF_VOCABW);
    const __nv_bfloat16* WhhF    = (const __nv_bfloat16*)(p + OFF_WHH);
    const __nv_bfloat16* WihF    = (const __nv_bfloat16*)(p + OFF_WIH);
    const __nv_bfloat16* projWF  = (const __nv_bfloat16*)(p + OFF_PROJW);
    const __nv_bfloat16* attnWF  = (const __nv_bfloat16*)(p + OFF_ATTNW);
    const __nv_bfloat16* ztransF = (const __nv_bfloat16*)(p + OFF_ZTRANSW);
    __nv_bfloat16* hbuf = (__nv_bfloat16*)(p + OFF_HBUF);
    float* rowsum = (float*)(p + OFF_ROWSUM);
    float* tgl    = (float*)(p + OFF_TGTL);
    int* h_done   = (int*)(p + OFF_FLAGS);
    int* vdone    = h_done + 16;
    volatile int* gxflag = (volatile int*)(h_done + 32);

    const int tid = threadIdx.x;
    const int lane = tid & 31;
    const int warp = tid >> 5;
    const int gid = lane >> 2, q = lane & 3;

    if (blockIdx.x < NRC) {
        // =================== RECURRENCE PATH (paired, row-local) ===========
        const int group = blockIdx.x >> 1;
        const int half  = blockIdx.x & 1;
        const int r0 = group * RPC;
        __nv_bfloat16* gxmine = (__nv_bfloat16*)(p + OFF_GX)
                              + ((size_t)group * 2 + half) * RPC * 1024;
        const __nv_bfloat16* gxpeer = (const __nv_bfloat16*)(p + OFF_GX)
                              + ((size_t)group * 2 + (half ^ 1)) * RPC * 1024;

        __nv_bfloat16* sFeat = (__nv_bfloat16*)(sp + SM_FEAT);
        __nv_bfloat16* sH    = (__nv_bfloat16*)(sp + SM_H);
        __nv_bfloat16* sZ    = (__nv_bfloat16*)(sp + SM_Z);
        __nv_bfloat16* sX    = (__nv_bfloat16*)(sp + SM_X);
        float*         sPre  = (float*)(sp + SM_PRE);
        __nv_bfloat16* sG    = (__nv_bfloat16*)(sp + SM_G);

        for (int i = tid; i < RPC * FEAT; i += NTHR) {
            int r = i >> 9, k = i & 511;
            sFeat[frag_off(r, k, FEAT)] = __float2bfloat16(features[(r0 + r) * FEAT + k]);
        }
        float c[16];
#pragma unroll
        for (int j = 0; j < 16; j++) c[j] = 0.f;
        __syncthreads();

        // h0 = feat @ projW^T + proj_b  (duplicated in both halves)
        {
            int n0 = warp * 32;
            float acc[4][4];
#pragma unroll
            for (int i = 0; i < 4; i++) { acc[i][0]=acc[i][1]=acc[i][2]=acc[i][3]=0.f; }
            tile16x32<16>(sFeat, projWF + (size_t)(n0 >> 3) * 16 * 256, lane, acc);
#pragma unroll
            for (int ci = 0; ci < 2; ci++) {
                int r = gid + ci * 8;
#pragma unroll
                for (int ni = 0; ni < 4; ni++) {
                    int col = n0 + ni * 8 + q * 2;
                    float v0 = acc[ni][ci * 2 + 0] + proj_b[col];
                    float v1 = acc[ni][ci * 2 + 1] + proj_b[col + 1];
                    *(uint32_t*)&sH[frag_off(r, col, HIDDEN)] = bf2_to_u32(v0, v1);
                }
            }
        }
        __syncthreads();

        for (int t = -1; t < TSTEPS; t++) {
            if (t >= 0) {
                // x = embed[word_t] + z @ ztransW^T + ztrans_b  (dup, warps 0..7)
                if (warp < 8) {
                    int n0 = warp * 32;
                    float acc[4][4];
#pragma unroll
                    for (int i = 0; i < 4; i++) { acc[i][0]=acc[i][1]=acc[i][2]=acc[i][3]=0.f; }
                    tile16x32<16>(sZ, ztransF + (size_t)(n0 >> 3) * 16 * 256, lane, acc);
#pragma unroll
                    for (int ci = 0; ci < 2; ci++) {
                        int r = gid + ci * 8;
                        int word = captions[(r0 + r) * CAPLEN + t];
#pragma unroll
                        for (int ni = 0; ni < 4; ni++) {
                            int col = n0 + ni * 8 + q * 2;
                            float v0 = acc[ni][ci*2+0] + ztrans_b[col]   + embed_W[(size_t)word * WVEC + col];
                            float v1 = acc[ni][ci*2+1] + ztrans_b[col+1] + embed_W[(size_t)word * WVEC + col + 1];
                            *(uint32_t*)&sX[frag_off(r, col, WVEC)] = bf2_to_u32(v0, v1);
                        }
                    }
                }
                __syncthreads();

                // gates HALF: this CTA computes cols [half*1024, half*1024+1024)
                {
                    int nloc = warp * 64;
                    int n0g = half * 1024 + nloc;
                    float acc[8][4];
#pragma unroll
                    for (int i = 0; i < 8; i++) { acc[i][0]=acc[i][1]=acc[i][2]=acc[i][3]=0.f; }
                    tile16x64<8>(sX, WihF + (size_t)(n0g >> 3) * 8 * 256, lane, acc);
                    tile16x64<16>(sH, WhhF + (size_t)(n0g >> 3) * 16 * 256, lane, acc);
#pragma unroll
                    for (int ci = 0; ci < 2; ci++) {
                        int r = gid + ci * 8;
#pragma unroll
                        for (int ni = 0; ni < 8; ni++) {
                            int col = n0g + ni * 8 + q * 2;
                            float v0 = acc[ni][ci*2+0] + b_ih[col]   + b_hh[col];
                            float v1 = acc[ni][ci*2+1] + b_ih[col+1] + b_hh[col+1];
                            uint32_t pr = bf2_to_u32(v0, v1);
                            *(uint32_t*)&sG[r * 2048 + col] = pr;
                            *(uint32_t*)&gxmine[r * 1024 + nloc + ni * 8 + q * 2] = pr;
                        }
                    }
                }
                __threadfence();
                __syncthreads();
                if (tid == 0) {
                    gxflag[group * 2 + half] = t + 1;           // publish my half
                    while (gxflag[group * 2 + (half ^ 1)] < t + 1) __nanosleep(64);
                }
                __syncthreads();
                __threadfence();
                // pull peer half into sG
                {
                    const uint4* s4 = (const uint4*)gxpeer;
                    int ph = (half ^ 1) * 1024;
                    for (int i = tid; i < RPC * 128; i += NTHR) {
                        int r = i >> 7, cw = i & 127;
                        *(uint4*)&sG[r * 2048 + ph + cw * 8] = s4[i];
                    }
                }
                __syncthreads();

                // LSTM cell (duplicated; identical bf16 inputs -> identical c,h)
                __nv_bfloat16* hT = hbuf + (size_t)t * BATCH * HIDDEN;
#pragma unroll
                for (int j = 0; j < 16; j++) {
                    int i = tid + j * NTHR;
                    int r = i >> 9, u = i & 511;
                    float ig = sigmoidf_(__bfloat162float(sG[r * 2048 + u]));
                    float fg = sigmoidf_(__bfloat162float(sG[r * 2048 + 512 + u]));
                    float gg = tanhf(__bfloat162float(sG[r * 2048 + 1024 + u]));
                    float og = sigmoidf_(__bfloat162float(sG[r * 2048 + 1536 + u]));
                    float cn = fg * c[j] + ig * gg;
                    float hn = og * tanhf(cn);
                    c[j] = cn;
                    __nv_bfloat16 hb = __float2bfloat16(hn);
                    sH[frag_off(r, u, HIDDEN)] = hb;
                    if (half == 0) hT[frag_off(r0 + r, u, HIDDEN)] = hb;
                }
                __threadfence();
                __syncthreads();
                if (tid == 0 && half == 0) atomicAdd(&h_done[t], 1);
                if (t == TSTEPS - 1) break;
            }

            // pre = h @ attnW^T + attn_b  (dup)
            {
                int n0 = warp * 32;
                float acc[4][4];
#pragma unroll
                for (int i = 0; i < 4; i++) { acc[i][0]=acc[i][1]=acc[i][2]=acc[i][3]=0.f; }
                tile16x32<16>(sH, attnWF + (size_t)(n0 >> 3) * 16 * 256, lane, acc);
#pragma unroll
                for (int ci = 0; ci < 2; ci++) {
                    int r = gid + ci * 8;
#pragma unroll
                    for (int ni = 0; ni < 4; ni++) {
                        int col = n0 + ni * 8 + q * 2;
                        sPre[r * FEAT + col]     = acc[ni][ci*2+0] + attn_b[col];
                        sPre[r * FEAT + col + 1] = acc[ni][ci*2+1] + attn_b[col + 1];
                    }
                }
            }
            __syncthreads();

            // z = softmax(pre) * features  (dup; warp w -> row w)
            {
                float v[16];
                float mx = -1e30f;
#pragma unroll
                for (int j = 0; j < 16; j++) {
                    v[j] = sPre[warp * FEAT + j * 32 + lane];
                    mx = fmaxf(mx, v[j]);
                }
#pragma unroll
                for (int d = 16; d > 0; d >>= 1)
                    mx = fmaxf(mx, __shfl_xor_sync(0xffffffffu, mx, d));
                float sum = 0.f;
#pragma unroll
                for (int j = 0; j < 16; j++) { v[j] = __expf(v[j] - mx); sum += v[j]; }
#pragma unroll
                for (int d = 16; d > 0; d >>= 1)
                    sum += __shfl_xor_sync(0xffffffffu, sum, d);
                float inv = 1.f / sum;
#pragma unroll
                for (int j = 0; j < 16; j++) {
                    int f = j * 32 + lane;
                    sZ[frag_off(warp, f, FEAT)] =
                        __float2bfloat16(v[j] * inv * features[(r0 + warp) * FEAT + f]);
                }
            }
            __syncthreads();
        }
    } else {
        // =================== VOCAB CONSUMER PATH ===================
        float* rl = (float*)sp;   // per-CTA rowsum accumulator [256]
        const int nvc = gridDim.x - NRC;
        const int vw = (blockIdx.x - NRC) * 16 + warp;
        const int NW = nvc * 16;

        for (int t = 0; t < TSTEPS; t++) {
            if (tid == 0) {
                volatile int* hd = &h_done[t];
                while (*hd < NGRP) __nanosleep(128);
            }
            for (int i = tid; i < BATCH; i += NTHR) rl[i] = 0.f;
            __syncthreads();
            __threadfence();

            const __nv_bfloat16* hT = hbuf + (size_t)t * BATCH * HIDDEN;
            const int* tgtB = captions + t + 1;
            float* rs_t  = rowsum + t * BATCH;
            float* tgl_t = tgl + t * BATCH;

            for (int tile = vw; tile < 4000; tile += NW) {
                int m0 = (tile & 3) * 64, n0 = (tile >> 2) * 32;

                const uint4* Ap = (const uint4*)(hT + (size_t)(m0 >> 3) * 16 * 256) + lane;
                const uint4* Bp = (const uint4*)(vocabW + (size_t)(n0 >> 3) * 16 * 256) + lane;

                float acc[4][4][4];
#pragma unroll
                for (int i = 0; i < 4; i++)
#pragma unroll
                    for (int j2 = 0; j2 < 4; j2++)
#pragma unroll
                        for (int k2 = 0; k2 < 4; k2++) acc[i][j2][k2] = 0.f;

                uint4 b0[4], b1[4];
#pragma unroll
                for (int ni = 0; ni < 4; ni++) b0[ni] = Bp[ni * 512];
#pragma unroll
                for (int it = 0; it < 16; it += 2) {
#pragma unroll
                    for (int ni = 0; ni < 4; ni++) b1[ni] = Bp[ni * 512 + (it + 1) * 32];
#pragma unroll
                    for (int mi = 0; mi < 4; mi++) {
                        uint4 al = Ap[mi * 1024 + it * 32];
                        uint4 ah = Ap[mi * 1024 + 512 + it * 32];
#pragma unroll
                        for (int ni = 0; ni < 4; ni++) {
                            mma16816(acc[mi][ni], al.x, ah.x, al.y, ah.y, b0[ni].x, b0[ni].y);
                            mma16816(acc[mi][ni], al.z, ah.z, al.w, ah.w, b0[ni].z, b0[ni].w);
                        }
                    }
                    if (it + 2 < 16) {
#pragma unroll
                        for (int ni = 0; ni < 4; ni++) b0[ni] = Bp[ni * 512 + (it + 2) * 32];
                    }
#pragma unroll
                    for (int mi = 0; mi < 4; mi++) {
                        uint4 al = Ap[mi * 1024 + (it + 1) * 32];
                        uint4 ah = Ap[mi * 1024 + 512 + (it + 1) * 32];
#pragma unroll
                        for (int ni = 0; ni < 4; ni++) {
                            mma16816(acc[mi][ni], al.x, ah.x, al.y, ah.y, b1[ni].x, b1[ni].y);
                            mma16816(acc[mi][ni], al.z, ah.z, al.w, ah.w, b1[ni].z, b1[ni].w);
                        }
                    }
                }
#pragma unroll
                for (int mi = 0; mi < 4; mi++)
#pragma unroll
                    for (int ci = 0; ci < 2; ci++) {
                        int row = m0 + mi * 16 + gid + ci * 8;
                        int tgt = tgtB[row * CAPLEN];
                        float s = 0.f;
#pragma unroll
                        for (int ni = 0; ni < 4; ni++)
#pragma unroll
                            for (int cj = 0; cj < 2; cj++) {
                                int col = n0 + ni * 8 + q * 2 + cj;
                                float v = acc[mi][ni][ci * 2 + cj] + vocab_b[col];
                                s += __expf(v);
                                if (col == tgt) tgl_t[row] = v;  // unique writer
                            }
                        s += __shfl_xor_sync(0xffffffffu, s, 1);
                        s += __shfl_xor_sync(0xffffffffu, s, 2);
                        if (q == 0) atomicAdd(&rl[row], s);
                    }
            }
            __syncthreads();
            for (int i = tid; i < BATCH; i += NTHR) atomicAdd(&rs_t[i], rl[i]);
            __threadfence();
            __syncthreads();
            if (tid == 0) {
                int d = atomicAdd(&vdone[t], 1);
                s_last = (d == nvc - 1) ? 1 : 0;
            }
            __syncthreads();
            if (s_last) {
                __threadfence();
                for (int r = tid; r < BATCH; r += NTHR) {
                    int tg = tgtB[r * CAPLEN];
                    if (tg != 0) {
                        float rs = *((volatile float*)&rs_t[r]);
                        float tv = *((volatile float*)&tgl_t[r]);
                        atomicAdd(out, (logf(rs) - tv) * (1.f / BATCH));
                    }
                }
            }
        }
    }
}

// ---------------------------------------------------------------------------
// One-shot: all fp32 weights -> bf16 frag layout, plus zeroing of
// rowsum / tgl / flags / out. Granule = 8 elements (16B destination).
// ---------------------------------------------------------------------------
constexpr int SEG0 = 2048000;           // vocabW  K=512
constexpr int SEG1 = SEG0 + 131072;     // Whh     K=512
constexpr int SEG2 = SEG1 + 65536;      // Wih     K=256
constexpr int SEG3 = SEG2 + 32768;      // projW   K=512
constexpr int SEG4 = SEG3 + 32768;      // attnW   K=512
constexpr int SEG5 = SEG4 + 16384;      // ztransW K=512
constexpr int CVT_TOTAL = SEG5 + 8257;  // + zero tail (rowsum|tgl|flags|out)

__global__ void convert_all_kernel(const float* __restrict__ vocab_W,
                                   const float* __restrict__ W_hh,
                                   const float* __restrict__ W_ih,
                                   const float* __restrict__ proj_W,
                                   const float* __restrict__ attn_W,
                                   const float* __restrict__ ztrans_W,
                                   float* __restrict__ out)
{
    int g = blockIdx.x * blockDim.x + threadIdx.x;
    if (g >= CVT_TOTAL) return;
    char* p = (char*)g_scratch;
    if (g >= SEG5) {  // zero tail
        int idx = g - SEG5;
        if (idx < 4096) ((float*)(p + OFF_ROWSUM))[idx] = 0.f;
        else if (idx < 8192) ((float*)(p + OFF_TGTL))[idx - 4096] = 0.f;
        else if (idx < 8256) ((int*)(p + OFF_FLAGS))[idx - 8192] = 0;
        else out[0] = 0.f;
        return;
    }
    const float* src;
    __nv_bfloat16* dst;
    int K;
    if (g < SEG0)      { src = vocab_W;  dst = (__nv_bfloat16*)(p + OFF_VOCABW);  K = 512; }
    else if (g < SEG1) { g -= SEG0; src = W_hh;     dst = (__nv_bfloat16*)(p + OFF_WHH);     K = 512; }
    else if (g < SEG2) { g -= SEG1; src = W_ih;     dst = (__nv_bfloat16*)(p + OFF_WIH);     K = 256; }
    else if (g < SEG3) { g -= SEG2; src = proj_W;   dst = (__nv_bfloat16*)(p + OFF_PROJW);   K = 512; }
    else if (g < SEG4) { g -= SEG3; src = attn_W;   dst = (__nv_bfloat16*)(p + OFF_ATTNW);   K = 512; }
    else               { g -= SEG4; src = ztrans_W; dst = (__nv_bfloat16*)(p + OFF_ZTRANSW); K = 512; }
    int kq = K >> 3;
    int row = g / kq;
    int k = (g - row * kq) * 8;
    const float* s = src + (size_t)row * K + k;
    float4 f0 = *(const float4*)s;
    float4 f1 = *(const float4*)(s + 4);
    uint4 o;
    o.x = bf2_to_u32(f0.x, f0.y);
    o.y = bf2_to_u32(f0.z, f0.w);
    o.z = bf2_to_u32(f1.x, f1.y);
    o.w = bf2_to_u32(f1.z, f1.w);
    *(uint4*)(dst + frag_off(row, k, K)) = o;
}

// ---------------------------------------------------------------------------
// Host launcher — 2 launches, graph-capturable, allocation-free
// ---------------------------------------------------------------------------
extern "C" void kernel_launch(void* const* d_in, const int* in_sizes, int n_in,
                              void* d_out, int out_size)
{
    (void)in_sizes; (void)n_in; (void)out_size;
    const float* features = (const float*)d_in[0];
    const int*   captions = (const int*)d_in[1];
    const float* embed_W  = (const float*)d_in[2];
    const float* proj_W   = (const float*)d_in[3];
    const float* proj_b   = (const float*)d_in[4];
    const float* vocab_W  = (const float*)d_in[5];
    const float* vocab_b  = (const float*)d_in[6];
    const float* attn_W   = (const float*)d_in[7];
    const float* attn_b   = (const float*)d_in[8];
    const float* ztrans_W = (const float*)d_in[9];
    const float* ztrans_b = (const float*)d_in[10];
    const float* W_ih     = (const float*)d_in[11];
    const float* W_hh     = (const float*)d_in[12];
    const float* b_ih     = (const float*)d_in[13];
    const float* b_hh     = (const float*)d_in[14];
    float* out = (float*)d_out;

    int dev = 0;
    cudaGetDevice(&dev);
    int sms = 0;
    cudaDeviceGetAttribute(&sms, cudaDevAttrMultiProcessorCount, dev);
    if (sms < 48) sms = 148;

    cudaFuncSetAttribute(mega_kernel, cudaFuncAttributeMaxDynamicSharedMemorySize, SMEM_BYTES);

    convert_all_kernel<<<(CVT_TOTAL + 255) / 256, 256>>>(
        vocab_W, W_hh, W_ih, proj_W, attn_W, ztrans_W, out);

    mega_kernel<<<sms, NTHR, SMEM_BYTES>>>(features, captions, embed_W,
                                           proj_b, vocab_b, attn_b, ztrans_b,
                                           b_ih, b_hh, out);
}

// round 14
// speedup vs baseline: 1.1763x; 1.1763x over previous
#include <cuda_runtime.h>
#include <cuda_bf16.h>
#include <cstdint>

#define BATCH   256
#define FEAT    512
#define HIDDEN  512
#define WVEC    256
#define VOCAB   32000
#define TSTEPS  16
#define CAPLEN  17
#define NRC     16          // recurrence CTAs
#define RPC     16          // batch rows per recurrence CTA
#define NTHR    512

// ---------------------------------------------------------------------------
// Fragment-native layout: element (row,k) of a [R][K] bf16 matrix lives at
//   ((row/8)*(K/32) + k/32)*256 + ((row%8)*4 + (k/8)%4)*8 + (k%8)   [elements]
// One warp's 8-row x 32-k fragment = 32 consecutive 16B granules (lane = slot).
// ---------------------------------------------------------------------------
__device__ __forceinline__ size_t frag_off(int row, int k, int K) {
    return ((size_t)(row >> 3) * (K >> 5) + (k >> 5)) * 256
         + (size_t)(((row & 7) * 4 + ((k >> 3) & 3)) * 8 + (k & 7));
}

// ---------------------------------------------------------------------------
// Scratch
// ---------------------------------------------------------------------------
constexpr size_t OFF_VOCABW  = 0;                                             // 32000x512 bf16
constexpr size_t OFF_WHH     = OFF_VOCABW  + (size_t)VOCAB * HIDDEN * 2;      // 2048x512
constexpr size_t OFF_WIH     = OFF_WHH     + (size_t)4 * HIDDEN * HIDDEN * 2; // 2048x256
constexpr size_t OFF_PROJW   = OFF_WIH     + (size_t)4 * HIDDEN * WVEC * 2;   // 512x512
constexpr size_t OFF_ATTNW   = OFF_PROJW   + (size_t)HIDDEN * FEAT * 2;       // 512x512
constexpr size_t OFF_ZTRANSW = OFF_ATTNW   + (size_t)FEAT * HIDDEN * 2;       // 256x512
constexpr size_t OFF_HBUF    = OFF_ZTRANSW + (size_t)WVEC * FEAT * 2;         // 16 x 256x512 bf16
constexpr size_t OFF_ROWSUM  = OFF_HBUF    + (size_t)TSTEPS * BATCH * HIDDEN * 2;
constexpr size_t OFF_TGTL    = OFF_ROWSUM  + (size_t)TSTEPS * BATCH * 4;
constexpr size_t OFF_FLAGS   = OFF_TGTL    + (size_t)TSTEPS * BATCH * 4;  // h_done[16]|vdone[16]
constexpr size_t SCRATCH_TOTAL = OFF_FLAGS + 256;

__device__ __align__(1024) unsigned char g_scratch[SCRATCH_TOTAL];

// smem carve (dynamic), bytes — recurrence CTAs
constexpr int SM_FEAT  = 0;       // 16x512 bf16 frag  (16K)
constexpr int SM_H     = 16384;   // 16x512 bf16 frag  (16K)
constexpr int SM_Z     = 32768;   // 16x512 bf16 frag  (16K)
constexpr int SM_X     = 49152;   // 16x256 bf16 frag  (8K)
constexpr int SM_PRE   = 57344;   // 16x512 f32        (32K)
constexpr int SM_G     = 90112;   // 16x2048 bf16 rowmajor (64K)
constexpr int SMEM_BYTES = 155648;

// ---------------------------------------------------------------------------
// mma.sync bf16 core
// ---------------------------------------------------------------------------
__device__ __forceinline__ float sigmoidf_(float x) { return 1.f / (1.f + __expf(-x)); }

__device__ __forceinline__ uint32_t bf2_to_u32(float lo, float hi) {
    __nv_bfloat162 b = __floats2bfloat162_rn(lo, hi);
    return *reinterpret_cast<uint32_t*>(&b);
}

__device__ __forceinline__ void mma16816(float c[4], uint32_t a0, uint32_t a1,
                                         uint32_t a2, uint32_t a3, uint32_t b0, uint32_t b1) {
    asm volatile(
        "mma.sync.aligned.m16n8k16.row.col.f32.bf16.bf16.f32 "
        "{%0,%1,%2,%3},{%4,%5,%6,%7},{%8,%9},{%0,%1,%2,%3};\n"
        : "+f"(c[0]), "+f"(c[1]), "+f"(c[2]), "+f"(c[3])
        : "r"(a0), "r"(a1), "r"(a2), "r"(a3), "r"(b0), "r"(b1));
}

// Pipelined 16(M) x 32(N) warp tile, ACCUMULATING into acc.
// Ap/Bp are uint4 granule pointers already offset by +lane.
// B is ping-pong prefetched one k-iteration ahead (low reg cost: acc16+B32).
template <int KB>
__device__ __forceinline__ void tile16x32p(const uint4* __restrict__ Ap,
                                           const uint4* __restrict__ Bp,
                                           float acc[4][4]) {
    uint4 b0[4], b1[4];
#pragma unroll
    for (int ni = 0; ni < 4; ni++) b0[ni] = Bp[ni * KB * 32];
#pragma unroll
    for (int it = 0; it < KB; it += 2) {
#pragma unroll
        for (int ni = 0; ni < 4; ni++) b1[ni] = Bp[ni * KB * 32 + (it + 1) * 32];
        {
            uint4 al = Ap[it * 32];
            uint4 ah = Ap[KB * 32 + it * 32];
#pragma unroll
            for (int ni = 0; ni < 4; ni++) {
                mma16816(acc[ni], al.x, ah.x, al.y, ah.y, b0[ni].x, b0[ni].y);
                mma16816(acc[ni], al.z, ah.z, al.w, ah.w, b0[ni].z, b0[ni].w);
            }
        }
        if (it + 2 < KB) {
#pragma unroll
            for (int ni = 0; ni < 4; ni++) b0[ni] = Bp[ni * KB * 32 + (it + 2) * 32];
        }
        {
            uint4 al = Ap[(it + 1) * 32];
            uint4 ah = Ap[KB * 32 + (it + 1) * 32];
#pragma unroll
            for (int ni = 0; ni < 4; ni++) {
                mma16816(acc[ni], al.x, ah.x, al.y, ah.y, b1[ni].x, b1[ni].y);
                mma16816(acc[ni], al.z, ah.z, al.w, ah.w, b1[ni].z, b1[ni].w);
            }
        }
    }
}

// ---------------------------------------------------------------------------
// Persistent heterogeneous kernel: CTAs 0..15 = recurrence (row-local),
// CTAs 16.. = vocab consumers (producer-consumer on h_done flags).
// ---------------------------------------------------------------------------
__global__ void __launch_bounds__(NTHR)
mega_kernel(const float* __restrict__ features, const int* __restrict__ captions,
            const float* __restrict__ embed_W,
            const float* __restrict__ proj_b, const float* __restrict__ vocab_b,
            const float* __restrict__ attn_b, const float* __restrict__ ztrans_b,
            const float* __restrict__ b_ih, const float* __restrict__ b_hh,
            float* __restrict__ out)
{
    extern __shared__ char sp[];
    __shared__ int s_last;
    char* p = (char*)g_scratch;
    const __nv_bfloat16* vocabW  = (const __nv_bfloat16*)(p + OFF_VOCABW);
    const __nv_bfloat16* WhhF    = (const __nv_bfloat16*)(p + OFF_WHH);
    const __nv_bfloat16* WihF    = (const __nv_bfloat16*)(p + OFF_WIH);
    const __nv_bfloat16* projWF  = (const __nv_bfloat16*)(p + OFF_PROJW);
    const __nv_bfloat16* attnWF  = (const __nv_bfloat16*)(p + OFF_ATTNW);
    const __nv_bfloat16* ztransF = (const __nv_bfloat16*)(p + OFF_ZTRANSW);
    __nv_bfloat16* hbuf = (__nv_bfloat16*)(p + OFF_HBUF);
    float* rowsum = (float*)(p + OFF_ROWSUM);
    float* tgl    = (float*)(p + OFF_TGTL);
    int* h_done   = (int*)(p + OFF_FLAGS);
    int* vdone    = h_done + 16;

    const int tid = threadIdx.x;
    const int lane = tid & 31;
    const int warp = tid >> 5;
    const int gid = lane >> 2, q = lane & 3;

    if (blockIdx.x < NRC) {
        // =================== RECURRENCE PATH (row-local) ===================
        const int r0 = blockIdx.x * RPC;
        __nv_bfloat16* sFeat = (__nv_bfloat16*)(sp + SM_FEAT);
        __nv_bfloat16* sH    = (__nv_bfloat16*)(sp + SM_H);
        __nv_bfloat16* sZ    = (__nv_bfloat16*)(sp + SM_Z);
        __nv_bfloat16* sX    = (__nv_bfloat16*)(sp + SM_X);
        float*         sPre  = (float*)(sp + SM_PRE);
        __nv_bfloat16* sG    = (__nv_bfloat16*)(sp + SM_G);

        for (int i = tid; i < RPC * FEAT; i += NTHR) {
            int r = i >> 9, k = i & 511;
            sFeat[frag_off(r, k, FEAT)] = __float2bfloat16(features[(r0 + r) * FEAT + k]);
        }
        float c[16];
#pragma unroll
        for (int j = 0; j < 16; j++) c[j] = 0.f;
        __syncthreads();

        // h0 = feat @ projW^T + proj_b
        {
            int n0 = warp * 32;
            float acc[4][4];
#pragma unroll
            for (int i = 0; i < 4; i++) { acc[i][0]=acc[i][1]=acc[i][2]=acc[i][3]=0.f; }
            tile16x32p<16>((const uint4*)sFeat + lane,
                           (const uint4*)(projWF + (size_t)(n0 >> 3) * 16 * 256) + lane, acc);
#pragma unroll
            for (int ci = 0; ci < 2; ci++) {
                int r = gid + ci * 8;
#pragma unroll
                for (int ni = 0; ni < 4; ni++) {
                    int col = n0 + ni * 8 + q * 2;
                    float v0 = acc[ni][ci * 2 + 0] + proj_b[col];
                    float v1 = acc[ni][ci * 2 + 1] + proj_b[col + 1];
                    *(uint32_t*)&sH[frag_off(r, col, HIDDEN)] = bf2_to_u32(v0, v1);
                }
            }
        }
        __syncthreads();

        for (int t = -1; t < TSTEPS; t++) {
            if (t >= 0) {
                // x = embed[word_t] + z @ ztransW^T + ztrans_b  (warps 0..7)
                if (warp < 8) {
                    int n0 = warp * 32;
                    float acc[4][4];
#pragma unroll
                    for (int i = 0; i < 4; i++) { acc[i][0]=acc[i][1]=acc[i][2]=acc[i][3]=0.f; }
                    tile16x32p<16>((const uint4*)sZ + lane,
                                   (const uint4*)(ztransF + (size_t)(n0 >> 3) * 16 * 256) + lane, acc);
#pragma unroll
                    for (int ci = 0; ci < 2; ci++) {
                        int r = gid + ci * 8;
                        int word = captions[(r0 + r) * CAPLEN + t];
#pragma unroll
                        for (int ni = 0; ni < 4; ni++) {
                            int col = n0 + ni * 8 + q * 2;
                            float v0 = acc[ni][ci*2+0] + ztrans_b[col]   + embed_W[(size_t)word * WVEC + col];
                            float v1 = acc[ni][ci*2+1] + ztrans_b[col+1] + embed_W[(size_t)word * WVEC + col + 1];
                            *(uint32_t*)&sX[frag_off(r, col, WVEC)] = bf2_to_u32(v0, v1);
                        }
                    }
                }
                __syncthreads();

                // gates = x @ Wih^T + h @ Whh^T + b_ih + b_hh
                // 4 pipelined 16x32 passes per warp (cols warp*128 .. +128)
#pragma unroll 1
                for (int pass = 0; pass < 4; pass++) {
                    int n0g = warp * 128 + pass * 32;
                    float acc[4][4];
#pragma unroll
                    for (int i = 0; i < 4; i++) { acc[i][0]=acc[i][1]=acc[i][2]=acc[i][3]=0.f; }
                    tile16x32p<8>((const uint4*)sX + lane,
                                  (const uint4*)(WihF + (size_t)(n0g >> 3) * 8 * 256) + lane, acc);
                    tile16x32p<16>((const uint4*)sH + lane,
                                   (const uint4*)(WhhF + (size_t)(n0g >> 3) * 16 * 256) + lane, acc);
#pragma unroll
                    for (int ci = 0; ci < 2; ci++) {
                        int r = gid + ci * 8;
#pragma unroll
                        for (int ni = 0; ni < 4; ni++) {
                            int col = n0g + ni * 8 + q * 2;
                            float v0 = acc[ni][ci*2+0] + b_ih[col]   + b_hh[col];
                            float v1 = acc[ni][ci*2+1] + b_ih[col+1] + b_hh[col+1];
                            *(uint32_t*)&sG[r * 2048 + col] = bf2_to_u32(v0, v1);
                        }
                    }
                }
                __syncthreads();

                // LSTM cell -> c (regs), h (smem frag + per-step global)
                __nv_bfloat16* hT = hbuf + (size_t)t * BATCH * HIDDEN;
#pragma unroll
                for (int j = 0; j < 16; j++) {
                    int i = tid + j * NTHR;
                    int r = i >> 9, u = i & 511;
                    float ig = sigmoidf_(__bfloat162float(sG[r * 2048 + u]));
                    float fg = sigmoidf_(__bfloat162float(sG[r * 2048 + 512 + u]));
                    float gg = tanhf(__bfloat162float(sG[r * 2048 + 1024 + u]));
                    float og = sigmoidf_(__bfloat162float(sG[r * 2048 + 1536 + u]));
                    float cn = fg * c[j] + ig * gg;
                    float hn = og * tanhf(cn);
                    c[j] = cn;
                    __nv_bfloat16 hb = __float2bfloat16(hn);
                    sH[frag_off(r, u, HIDDEN)] = hb;
                    hT[frag_off(r0 + r, u, HIDDEN)] = hb;
                }
                __threadfence();
                __syncthreads();
                if (tid == 0) atomicAdd(&h_done[t], 1);
                if (t == TSTEPS - 1) break;
            }

            // pre = h @ attnW^T + attn_b
            {
                int n0 = warp * 32;
                float acc[4][4];
#pragma unroll
                for (int i = 0; i < 4; i++) { acc[i][0]=acc[i][1]=acc[i][2]=acc[i][3]=0.f; }
                tile16x32p<16>((const uint4*)sH + lane,
                               (const uint4*)(attnWF + (size_t)(n0 >> 3) * 16 * 256) + lane, acc);
#pragma unroll
                for (int ci = 0; ci < 2; ci++) {
                    int r = gid + ci * 8;
#pragma unroll
                    for (int ni = 0; ni < 4; ni++) {
                        int col = n0 + ni * 8 + q * 2;
                        sPre[r * FEAT + col]     = acc[ni][ci*2+0] + attn_b[col];
                        sPre[r * FEAT + col + 1] = acc[ni][ci*2+1] + attn_b[col + 1];
                    }
                }
            }
            __syncthreads();

            // z = softmax(pre) * features  (warp w -> row w)
            {
                float v[16];
                float mx = -1e30f;
#pragma unroll
                for (int j = 0; j < 16; j++) {
                    v[j] = sPre[warp * FEAT + j * 32 + lane];
                    mx = fmaxf(mx, v[j]);
                }
#pragma unroll
                for (int d = 16; d > 0; d >>= 1)
                    mx = fmaxf(mx, __shfl_xor_sync(0xffffffffu, mx, d));
                float sum = 0.f;
#pragma unroll
                for (int j = 0; j < 16; j++) { v[j] = __expf(v[j] - mx); sum += v[j]; }
#pragma unroll
                for (int d = 16; d > 0; d >>= 1)
                    sum += __shfl_xor_sync(0xffffffffu, sum, d);
                float inv = 1.f / sum;
#pragma unroll
                for (int j = 0; j < 16; j++) {
                    int f = j * 32 + lane;
                    sZ[frag_off(warp, f, FEAT)] =
                        __float2bfloat16(v[j] * inv * features[(r0 + warp) * FEAT + f]);
                }
            }
            __syncthreads();
        }
    } else {
        // =================== VOCAB CONSUMER PATH ===================
        float* rl = (float*)sp;   // per-CTA rowsum accumulator [256]
        const int nvc = gridDim.x - NRC;
        const int vw = (blockIdx.x - NRC) * 16 + warp;
        const int NW = nvc * 16;

        for (int t = 0; t < TSTEPS; t++) {
            if (tid == 0) {
                volatile int* hd = &h_done[t];
                while (*hd < NRC) __nanosleep(128);
            }
            for (int i = tid; i < BATCH; i += NTHR) rl[i] = 0.f;
            __syncthreads();
            __threadfence();

            const __nv_bfloat16* hT = hbuf + (size_t)t * BATCH * HIDDEN;
            const int* tgtB = captions + t + 1;
            float* rs_t  = rowsum + t * BATCH;
            float* tgl_t = tgl + t * BATCH;

            for (int tile = vw; tile < 4000; tile += NW) {
                int m0 = (tile & 3) * 64, n0 = (tile >> 2) * 32;

                const uint4* Ap = (const uint4*)(hT + (size_t)(m0 >> 3) * 16 * 256) + lane;
                const uint4* Bp = (const uint4*)(vocabW + (size_t)(n0 >> 3) * 16 * 256) + lane;

                float acc[4][4][4];
#pragma unroll
                for (int i = 0; i < 4; i++)
#pragma unroll
                    for (int j2 = 0; j2 < 4; j2++)
#pragma unroll
                        for (int k2 = 0; k2 < 4; k2++) acc[i][j2][k2] = 0.f;

                uint4 b0[4], b1[4];
#pragma unroll
                for (int ni = 0; ni < 4; ni++) b0[ni] = Bp[ni * 512];
#pragma unroll
                for (int it = 0; it < 16; it += 2) {
#pragma unroll
                    for (int ni = 0; ni < 4; ni++) b1[ni] = Bp[ni * 512 + (it + 1) * 32];
#pragma unroll
                    for (int mi = 0; mi < 4; mi++) {
                        uint4 al = Ap[mi * 1024 + it * 32];
                        uint4 ah = Ap[mi * 1024 + 512 + it * 32];
#pragma unroll
                        for (int ni = 0; ni < 4; ni++) {
                            mma16816(acc[mi][ni], al.x, ah.x, al.y, ah.y, b0[ni].x, b0[ni].y);
                            mma16816(acc[mi][ni], al.z, ah.z, al.w, ah.w, b0[ni].z, b0[ni].w);
                        }
                    }
                    if (it + 2 < 16) {
#pragma unroll
                        for (int ni = 0; ni < 4; ni++) b0[ni] = Bp[ni * 512 + (it + 2) * 32];
                    }
#pragma unroll
                    for (int mi = 0; mi < 4; mi++) {
                        uint4 al = Ap[mi * 1024 + (it + 1) * 32];
                        uint4 ah = Ap[mi * 1024 + 512 + (it + 1) * 32];
#pragma unroll
                        for (int ni = 0; ni < 4; ni++) {
                            mma16816(acc[mi][ni], al.x, ah.x, al.y, ah.y, b1[ni].x, b1[ni].y);
                            mma16816(acc[mi][ni], al.z, ah.z, al.w, ah.w, b1[ni].z, b1[ni].w);
                        }
                    }
                }
#pragma unroll
                for (int mi = 0; mi < 4; mi++)
#pragma unroll
                    for (int ci = 0; ci < 2; ci++) {
                        int row = m0 + mi * 16 + gid + ci * 8;
                        int tgt = tgtB[row * CAPLEN];
                        float s = 0.f;
#pragma unroll
                        for (int ni = 0; ni < 4; ni++)
#pragma unroll
                            for (int cj = 0; cj < 2; cj++) {
                                int col = n0 + ni * 8 + q * 2 + cj;
                                float v = acc[mi][ni][ci * 2 + cj] + vocab_b[col];
                                s += __expf(v);
                                if (col == tgt) tgl_t[row] = v;  // unique writer
                            }
                        s += __shfl_xor_sync(0xffffffffu, s, 1);
                        s += __shfl_xor_sync(0xffffffffu, s, 2);
                        if (q == 0) atomicAdd(&rl[row], s);
                    }
            }
            __syncthreads();
            for (int i = tid; i < BATCH; i += NTHR) atomicAdd(&rs_t[i], rl[i]);
            __threadfence();
            __syncthreads();
            if (tid == 0) {
                int d = atomicAdd(&vdone[t], 1);
                s_last = (d == nvc - 1) ? 1 : 0;
            }
            __syncthreads();
            if (s_last) {
                __threadfence();
                for (int r = tid; r < BATCH; r += NTHR) {
                    int tg = tgtB[r * CAPLEN];
                    if (tg != 0) {
                        float rs = *((volatile float*)&rs_t[r]);
                        float tv = *((volatile float*)&tgl_t[r]);
                        atomicAdd(out, (logf(rs) - tv) * (1.f / BATCH));
                    }
                }
            }
        }
    }
}

// ---------------------------------------------------------------------------
// One-shot: all fp32 weights -> bf16 frag layout, plus zeroing of
// rowsum / tgl / flags / out. Granule = 8 elements (16B destination).
// ---------------------------------------------------------------------------
constexpr int SEG0 = 2048000;           // vocabW  K=512
constexpr int SEG1 = SEG0 + 131072;     // Whh     K=512
constexpr int SEG2 = SEG1 + 65536;      // Wih     K=256
constexpr int SEG3 = SEG2 + 32768;      // projW   K=512
constexpr int SEG4 = SEG3 + 32768;      // attnW   K=512
constexpr int SEG5 = SEG4 + 16384;      // ztransW K=512
constexpr int CVT_TOTAL = SEG5 + 8241;  // + zero tail

__global__ void convert_all_kernel(const float* __restrict__ vocab_W,
                                   const float* __restrict__ W_hh,
                                   const float* __restrict__ W_ih,
                                   const float* __restrict__ proj_W,
                                   const float* __restrict__ attn_W,
                                   const float* __restrict__ ztrans_W,
                                   float* __restrict__ out)
{
    int g = blockIdx.x * blockDim.x + threadIdx.x;
    if (g >= CVT_TOTAL) return;
    char* p = (char*)g_scratch;
    if (g >= SEG5) {  // zero tail
        int idx = g - SEG5;
        if (idx < 4096) ((float*)(p + OFF_ROWSUM))[idx] = 0.f;
        else if (idx < 8192) ((float*)(p + OFF_TGTL))[idx - 4096] = 0.f;
        else if (idx < 8240) ((int*)(p + OFF_FLAGS))[idx - 8192] = 0;
        else out[0] = 0.f;
        return;
    }
    const float* src;
    __nv_bfloat16* dst;
    int K;
    if (g < SEG0)      { src = vocab_W;  dst = (__nv_bfloat16*)(p + OFF_VOCABW);  K = 512; }
    else if (g < SEG1) { g -= SEG0; src = W_hh;     dst = (__nv_bfloat16*)(p + OFF_WHH);     K = 512; }
    else if (g < SEG2) { g -= SEG1; src = W_ih;     dst = (__nv_bfloat16*)(p + OFF_WIH);     K = 256; }
    else if (g < SEG3) { g -= SEG2; src = proj_W;   dst = (__nv_bfloat16*)(p + OFF_PROJW);   K = 512; }
    else if (g < SEG4) { g -= SEG3; src = attn_W;   dst = (__nv_bfloat16*)(p + OFF_ATTNW);   K = 512; }
    else               { g -= SEG4; src = ztrans_W; dst = (__nv_bfloat16*)(p + OFF_ZTRANSW); K = 512; }
    int kq = K >> 3;
    int row = g / kq;
    int k = (g - row * kq) * 8;
    const float* s = src + (size_t)row * K + k;
    float4 f0 = *(const float4*)s;
    float4 f1 = *(const float4*)(s + 4);
    uint4 o;
    o.x = bf2_to_u32(f0.x, f0.y);
    o.y = bf2_to_u32(f0.z, f0.w);
    o.z = bf2_to_u32(f1.x, f1.y);
    o.w = bf2_to_u32(f1.z, f1.w);
    *(uint4*)(dst + frag_off(row, k, K)) = o;
}

// ---------------------------------------------------------------------------
// Host launcher — 2 launches, graph-capturable, allocation-free
// ---------------------------------------------------------------------------
extern "C" void kernel_launch(void* const* d_in, const int* in_sizes, int n_in,
                              void* d_out, int out_size)
{
    (void)in_sizes; (void)n_in; (void)out_size;
    const float* features = (const float*)d_in[0];
    const int*   captions = (const int*)d_in[1];
    const float* embed_W  = (const float*)d_in[2];
    const float* proj_W   = (const float*)d_in[3];
    const float* proj_b   = (const float*)d_in[4];
    const float* vocab_W  = (const float*)d_in[5];
    const float* vocab_b  = (const float*)d_in[6];
    const float* attn_W   = (const float*)d_in[7];
    const float* attn_b   = (const float*)d_in[8];
    const float* ztrans_W = (const float*)d_in[9];
    const float* ztrans_b = (const float*)d_in[10];
    const float* W_ih     = (const float*)d_in[11];
    const float* W_hh     = (const float*)d_in[12];
    const float* b_ih     = (const float*)d_in[13];
    const float* b_hh     = (const float*)d_in[14];
    float* out = (float*)d_out;

    int dev = 0;
    cudaGetDevice(&dev);
    int sms = 0;
    cudaDeviceGetAttribute(&sms, cudaDevAttrMultiProcessorCount, dev);
    if (sms < 32) sms = 148;

    cudaFuncSetAttribute(mega_kernel, cudaFuncAttributeMaxDynamicSharedMemorySize, SMEM_BYTES);

    convert_all_kernel<<<(CVT_TOTAL + 255) / 256, 256>>>(
        vocab_W, W_hh, W_ih, proj_W, attn_W, ztrans_W, out);

    mega_kernel<<<sms, NTHR, SMEM_BYTES>>>(features, captions, embed_W,
                                           proj_b, vocab_b, attn_b, ztrans_b,
                                           b_ih, b_hh, out);
}